// round 17
// baseline (speedup 1.0000x reference)
#include <cuda_runtime.h>
#include <cstdint>

#define B_    64
#define S_    2048
#define H_    1024
#define SPLIT 16
#define CHUNK (S_ / SPLIT)      // 128 timesteps per CTA
#define TILE  4
#define NTILES (CHUNK / TILE)   // 32
#define THREADS 256             // one float4 column slice per thread
#define WARPS (THREADS / 32)

// Scratch (allocation-free: __device__ globals)
__device__ float g_expE [B_ * S_];             // exp(tanh(score)) per (b,s)
__device__ float g_partL[B_ * SPLIT];          // partial sum of exp per chunk
__device__ float g_partC[B_ * SPLIT * H_];     // partial context per chunk (4 MiB)
__device__ int   g_count[B_];                  // arrival counter per batch

__device__ __forceinline__ float tanh_approx(float v) {
    float r;
    asm("tanh.approx.f32 %0, %1;" : "=f"(r) : "f"(v));
    return r;
}

// ---------------------------------------------------------------------------
// Fused kernel (R16 + occupancy push): the warp cap on sm_103a is 64/SM, and
// all 4-CTA variants sit at ~44% occ = 89% of a 32-warp ceiling. TILE=4 cuts
// the data-register budget in half; __launch_bounds__(256,6) targets ~42
// regs -> 6 CTAs/SM = 48 warps. Issue headroom is ample (~0.03 warp-instr
// per byte), so thinner/more CTAs raise DRAM duty without an issue wall.
// Per tile of 4 timesteps, thread t owns H columns [4t,4t+4):
//   1. 4 front-batched float4 loads (__ldcs, single-use streaming)
//   2. partial dots vs w4
//   3. interleaved 4-row warp reduce (9 SHFL); lane L<4 holds row L's sum
//   4. lane L publishes red[p][L][warp] (transposed layout, conflict-free);
//      ONE __syncthreads
//   5. redundant finish in every warp: lanes 0-3 read their row's 8 warp
//      partials as 2 LDS.128, t = __expf(tanh.approx(v+bias))
//      (tanh in [-1,1] -> softmax needs no max subtraction)
//   6. shuffle-broadcast t, acc += t*xr from registers
// Epilogue: threadfence-reduction; 16th CTA per batch reduces partials,
// writes context + weights (deterministic; counter reset by finisher).
// ---------------------------------------------------------------------------
__global__ __launch_bounds__(THREADS, 6)
void fused_kernel(const float* __restrict__ x,
                  const float* __restrict__ w,
                  const float* __restrict__ bptr,
                  float* __restrict__ ctx_out,
                  float* __restrict__ wts_out)
{
    __shared__ float red[2][TILE][WARPS];    // ping-pong, transposed [row][warp]
    __shared__ int   s_last;
    __shared__ float s_inv;

    const int b     = blockIdx.x / SPLIT;
    const int chunk = blockIdx.x % SPLIT;
    const int tid   = threadIdx.x;
    const int warp  = tid >> 5;
    const int lane  = tid & 31;
    const float bias = __ldg(bptr);
    const float4 w4 = reinterpret_cast<const float4*>(w)[tid];

    float4 acc = make_float4(0.f, 0.f, 0.f, 0.f);
    float lsum = 0.f;                        // warp 0, lanes 0-3 accumulate

    const int s0 = chunk * CHUNK;
    const float4* xp = reinterpret_cast<const float4*>(x) +
                       ((size_t)b * S_ + s0) * (H_ / 4) + tid;

    #pragma unroll 1
    for (int tile = 0; tile < NTILES; tile++) {
        const int p = tile & 1;

        // 1. front-batched streaming loads (MLP=4)
        float4 xr[TILE];
        #pragma unroll
        for (int s = 0; s < TILE; s++)
            xr[s] = __ldcs(&xp[(size_t)s * (H_ / 4)]);

        // 2. partial dots
        float d[TILE];
        #pragma unroll
        for (int s = 0; s < TILE; s++)
            d[s] = xr[s].x * w4.x + xr[s].y * w4.y
                 + xr[s].z * w4.z + xr[s].w * w4.w;

        // 3. interleaved 4-row warp reduce: 9 SHFL; lane L<4 ends with row L
        #pragma unroll
        for (int s = 0; s < TILE; s++)
            d[s] += __shfl_xor_sync(0xffffffffu, d[s], 1);
        float e0 = (lane & 1) ? d[1] : d[0];
        float e1 = (lane & 1) ? d[3] : d[2];
        e0 += __shfl_xor_sync(0xffffffffu, e0, 2);
        e1 += __shfl_xor_sync(0xffffffffu, e1, 2);
        float f = (lane & 2) ? e1 : e0;
        f += __shfl_xor_sync(0xffffffffu, f, 4);
        f += __shfl_xor_sync(0xffffffffu, f, 8);
        f += __shfl_xor_sync(0xffffffffu, f, 16);

        // 4. transposed publish: lane L -> red[p][L][warp] (banks w,8+w,16+w,24+w)
        if (lane < TILE)
            red[p][lane][warp] = f;

        __syncthreads();                      // single barrier per tile

        // 5. redundant finish: lanes 0-3 read row (lane)'s 8 warp partials
        //    as two float4 LDS (contiguous in the transposed layout)
        float t = 0.f;
        if (lane < TILE) {
            const float4* rr = reinterpret_cast<const float4*>(red[p][lane]);
            float4 a0 = rr[0];
            float4 a1 = rr[1];
            float v = ((a0.x + a0.y) + (a0.z + a0.w))
                    + ((a1.x + a1.y) + (a1.z + a1.w));
            t = __expf(tanh_approx(v + bias));
            if (warp == 0) {
                __stcg(&g_expE[(size_t)b * S_ + s0 + tile * TILE + lane], t);
                lsum += t;
            }
        }

        // 6. broadcast t and accumulate from registers
        #pragma unroll
        for (int s = 0; s < TILE; s++) {
            const float ts = __shfl_sync(0xffffffffu, t, s);
            acc.x += ts * xr[s].x;
            acc.y += ts * xr[s].y;
            acc.z += ts * xr[s].z;
            acc.w += ts * xr[s].w;
        }

        xp += TILE * (H_ / 4);               // advance base (fewer live addrs)
    }

    // flush partial context (L2-only: consumer is a different CTA)
    __stcg(&reinterpret_cast<float4*>(
               g_partC + ((size_t)b * SPLIT + chunk) * H_)[tid], acc);

    // warp 0: lanes 0-3 hold partial lsums -> in-warp reduce, lane 0 stores
    if (warp == 0) {
        lsum += __shfl_xor_sync(0xffffffffu, lsum, 1);
        lsum += __shfl_xor_sync(0xffffffffu, lsum, 2);
        if (lane == 0) __stcg(&g_partL[b * SPLIT + chunk], lsum);
    }

    // -------- finisher election (threadfence reduction pattern) --------
    __threadfence();
    __syncthreads();
    if (tid == 0) {
        const int old = atomicAdd(&g_count[b], 1);
        s_last = (old == SPLIT - 1);
        if (s_last) g_count[b] = 0;   // reset for next replay (all arrived)
    }
    __syncthreads();
    if (!s_last) return;
    __threadfence();                  // acquire: see peers' flushes

    // -------- epilogue: this CTA finishes batch b --------
    if (tid < 32) {
        float l = (tid < SPLIT) ? __ldcg(&g_partL[b * SPLIT + tid]) : 0.f;
        #pragma unroll
        for (int off = 16; off; off >>= 1)
            l += __shfl_xor_sync(0xffffffffu, l, off);
        if (tid == 0) s_inv = 1.f / l;
    }
    __syncthreads();
    const float inv = s_inv;

    // context[b][:] : 256 threads x one float4, 16 independent partial loads
    float4 c = make_float4(0.f, 0.f, 0.f, 0.f);
    #pragma unroll
    for (int cc = 0; cc < SPLIT; cc++) {
        float4 v = __ldcg(&reinterpret_cast<const float4*>(
            g_partC + ((size_t)b * SPLIT + cc) * H_)[tid]);
        c.x += v.x; c.y += v.y; c.z += v.z; c.w += v.w;
    }
    c.x *= inv; c.y *= inv; c.z *= inv; c.w *= inv;
    __stcs(&reinterpret_cast<float4*>(ctx_out)[b * (H_ / 4) + tid], c);

    // weights[b][:] : S/4 = 512 float4, 2 per thread
    #pragma unroll
    for (int i = 0; i < S_ / 4 / THREADS; i++) {
        const int idx = b * (S_ / 4) + i * THREADS + tid;
        float4 e = __ldcg(&reinterpret_cast<const float4*>(g_expE)[idx]);
        e.x *= inv; e.y *= inv; e.z *= inv; e.w *= inv;
        __stcs(&reinterpret_cast<float4*>(wts_out)[idx], e);
    }
}

extern "C" void kernel_launch(void* const* d_in, const int* in_sizes, int n_in,
                              void* d_out, int out_size)
{
    const float* x    = (const float*)d_in[0];   // rnn_output [B,S,H]
    const float* w    = (const float*)d_in[1];   // attn_w [H]
    const float* bptr = (const float*)d_in[2];   // attn_b scalar

    float* out = (float*)d_out;                  // context [B,H] then weights [B,S]
    float* ctx_out = out;
    float* wts_out = out + (size_t)B_ * H_;

    fused_kernel<<<B_ * SPLIT, THREADS>>>(x, w, bptr, ctx_out, wts_out);
}